// round 1
// baseline (speedup 1.0000x reference)
#include <cuda_runtime.h>
#include <cstdint>
#include <cstddef>

#define THREADS 128
#define MAX_NODES 50176

// den accumulator scratch (no cudaMalloc allowed)
__device__ float g_den[MAX_NODES];

// ---------- packed fp32x2 helpers (sm_103a) ----------
__device__ __forceinline__ unsigned long long pk2(float x, float y) {
    unsigned long long r;
    asm("mov.b64 %0, {%1, %2};" : "=l"(r) : "f"(x), "f"(y));
    return r;
}
__device__ __forceinline__ void upk2(unsigned long long v, float &x, float &y) {
    asm("mov.b64 {%0, %1}, %2;" : "=f"(x), "=f"(y) : "l"(v));
}
__device__ __forceinline__ unsigned long long ffma2(unsigned long long a,
                                                    unsigned long long b,
                                                    unsigned long long c) {
    unsigned long long d;
    asm("fma.rn.f32x2 %0, %1, %2, %3;" : "=l"(d) : "l"(a), "l"(b), "l"(c));
    return d;
}

// Shared-memory layout offsets (bytes)
#define OFF_XS    0        // 64*68 floats (xs tile, reused as msg tile stride-68)
#define OFF_HS    17408    // 64*64 floats
#define OFF_WP1   33792    // 32*64 u64
#define OFF_WP2   50176    // 32*64 u64
#define OFF_B1    66560    // 64 f
#define OFF_B2    66816    // 64 f
#define OFF_CF    67072    // 64 f
#define OFF_ATTN  67328    // 64 f
#define OFF_PART  67584    // 2*64 f
#define OFF_DEST  68096    // 64 i32
#define OFF_SRC   68352    // 64 i32
#define OFF_FLAG  68608    // 1 i32
#define SMEM_BYTES 68640

__global__ __launch_bounds__(THREADS, 3)
void cfconv_main(const float* __restrict__ atom_emb,
                 const float* __restrict__ edge_emb,
                 const float* __restrict__ W1, const float* __restrict__ b1,
                 const float* __restrict__ W2, const float* __restrict__ b2,
                 const float* __restrict__ coef,
                 const void*  __restrict__ edge_list,
                 float* __restrict__ num,
                 int nE)
{
    extern __shared__ unsigned char sraw[];
    float* xs                 = (float*)(sraw + OFF_XS);
    float* hs                 = (float*)(sraw + OFF_HS);
    unsigned long long* wp1   = (unsigned long long*)(sraw + OFF_WP1);
    unsigned long long* wp2   = (unsigned long long*)(sraw + OFF_WP2);
    float* b1s                = (float*)(sraw + OFF_B1);
    float* b2s                = (float*)(sraw + OFF_B2);
    float* cfs                = (float*)(sraw + OFF_CF);
    float* attn_s             = (float*)(sraw + OFF_ATTN);
    float* part_s             = (float*)(sraw + OFF_PART);
    int*   dest_s             = (int*)(sraw + OFF_DEST);
    int*   src_s              = (int*)(sraw + OFF_SRC);
    int*   flag_s             = (int*)(sraw + OFF_FLAG);

    const int tid = threadIdx.x;
    if (tid == 0) *flag_s = 0;
    __syncthreads();

    // Pack weights into even/odd k-row pairs per column: wp[j*64+c] = (W[2j][c], W[2j+1][c])
    for (int i = tid; i < 2048; i += THREADS) {
        int j = i >> 6, cc = i & 63;
        wp1[i] = pk2(W1[(2 * j) * 64 + cc], W1[(2 * j + 1) * 64 + cc]);
        wp2[i] = pk2(W2[(2 * j) * 64 + cc], W2[(2 * j + 1) * 64 + cc]);
    }
    if (tid < 64) { b1s[tid] = b1[tid]; b2s[tid] = b2[tid]; cfs[tid] = coef[tid]; }

    // Detect edge_list dtype: int64 => all odd 32-bit words (high halves) are 0.
    {
        const int* ei = (const int*)edge_list;
        if (tid < 64) {
            if (ei[2 * tid + 1] != 0) atomicOr(flag_s, 1);
        }
    }
    __syncthreads();
    const bool is32 = (*flag_s != 0);

    const int c    = tid & 63;          // output column this thread owns
    const int half = tid >> 6;          // which 32-edge half of the tile
    const int lane = tid & 31;
    const int wgrp = (tid >> 5) & 1;    // column group (c<32 or c>=32)
    const float b1c = b1s[c], b2c = b2s[c], cfc = cfs[c];

    const int nTiles = (nE + 63) >> 6;
    for (int t = blockIdx.x; t < nTiles; t += gridDim.x) {
        __syncthreads();   // protect xs (scatter of previous tile reads it)
        const int base = t << 6;

        // ---- load edge indices ----
        if (tid < 64) {
            int e = base + tid;
            int d = 0, s = 0;
            if (e < nE) {
                if (is32) {
                    int2 p = ((const int2*)edge_list)[e];
                    d = p.x; s = p.y;
                } else {
                    longlong2 p = ((const longlong2*)edge_list)[e];
                    d = (int)p.x; s = (int)p.y;
                }
            }
            dest_s[tid] = d; src_s[tid] = s;
        }
        // ---- load 64 edge_emb rows (tight stride-64 layout) ----
        for (int i = tid; i < 1024; i += THREADS) {
            int el = i >> 4, q = i & 15;
            int e = base + el;
            float4 v = make_float4(0.f, 0.f, 0.f, 0.f);
            if (e < nE) v = ((const float4*)edge_emb)[(size_t)e * 16 + q];
            *((float4*)(xs + el * 64) + q) = v;
        }
        __syncthreads();

        // ---- GEMM1: h1 = tanh(x @ W1 + b1) ----
        unsigned long long w[32];
        #pragma unroll
        for (int j = 0; j < 32; j++) w[j] = wp1[j * 64 + c];

        for (int ei2 = 0; ei2 < 32; ei2 += 2) {
            int e0 = half * 32 + ei2;
            const ulonglong2* r0 = (const ulonglong2*)(xs + e0 * 64);
            const ulonglong2* r1 = (const ulonglong2*)(xs + e0 * 64 + 64);
            unsigned long long a0e = 0ull, a0o = 0ull, a1e = 0ull, a1o = 0ull;
            #pragma unroll
            for (int k = 0; k < 16; k++) {
                ulonglong2 v0 = r0[k];
                ulonglong2 v1 = r1[k];
                a0e = ffma2(v0.x, w[2 * k],     a0e);
                a0o = ffma2(v0.y, w[2 * k + 1], a0o);
                a1e = ffma2(v1.x, w[2 * k],     a1e);
                a1o = ffma2(v1.y, w[2 * k + 1], a1o);
            }
            float s0, s1, s2, s3, s4, s5, s6, s7;
            upk2(a0e, s0, s1); upk2(a0o, s2, s3);
            upk2(a1e, s4, s5); upk2(a1o, s6, s7);
            hs[e0 * 64 + c]       = tanhf(s0 + s1 + s2 + s3 + b1c);
            hs[(e0 + 1) * 64 + c] = tanhf(s4 + s5 + s6 + s7 + b1c);
        }
        __syncthreads();

        // ---- GEMM2 + gather + msg + attn partial dot ----
        #pragma unroll
        for (int j = 0; j < 32; j++) w[j] = wp2[j * 64 + c];

        for (int ei2 = 0; ei2 < 32; ei2 += 2) {
            int e0 = half * 32 + ei2;
            float gg0 = __ldg(atom_emb + (size_t)src_s[e0] * 64 + c);
            float gg1 = __ldg(atom_emb + (size_t)src_s[e0 + 1] * 64 + c);

            const ulonglong2* r0 = (const ulonglong2*)(hs + e0 * 64);
            const ulonglong2* r1 = (const ulonglong2*)(hs + e0 * 64 + 64);
            unsigned long long a0e = 0ull, a0o = 0ull, a1e = 0ull, a1o = 0ull;
            #pragma unroll
            for (int k = 0; k < 16; k++) {
                ulonglong2 v0 = r0[k];
                ulonglong2 v1 = r1[k];
                a0e = ffma2(v0.x, w[2 * k],     a0e);
                a0o = ffma2(v0.y, w[2 * k + 1], a0o);
                a1e = ffma2(v1.x, w[2 * k],     a1e);
                a1o = ffma2(v1.y, w[2 * k + 1], a1o);
            }
            float s0, s1, s2, s3, s4, s5, s6, s7;
            upk2(a0e, s0, s1); upk2(a0o, s2, s3);
            upk2(a1e, s4, s5); upk2(a1o, s6, s7);
            float h20 = s0 + s1 + s2 + s3 + b2c;
            float h21 = s4 + s5 + s6 + s7 + b2c;
            float m0 = gg0 * h20;
            float m1 = gg1 * h21;
            // msg tile, stride 68 to dodge bank conflicts in scatter (reuses xs buffer)
            xs[e0 * 68 + c]       = m0;
            xs[(e0 + 1) * 68 + c] = m1;

            float p0 = m0 * cfc, p1 = m1 * cfc;
            #pragma unroll
            for (int o = 16; o > 0; o >>= 1) {
                p0 += __shfl_xor_sync(0xffffffffu, p0, o);
                p1 += __shfl_xor_sync(0xffffffffu, p1, o);
            }
            if (lane == 0) {
                part_s[wgrp * 64 + e0]     = p0;
                part_s[wgrp * 64 + e0 + 1] = p1;
            }
        }
        __syncthreads();

        // ---- attn = exp(msg . coef), accumulate den ----
        if (tid < 64) {
            int e = base + tid;
            float a = 0.f;
            if (e < nE) {
                a = expf(part_s[tid] + part_s[64 + tid]);
                atomicAdd(&g_den[dest_s[tid]], a);
            }
            attn_s[tid] = a;
        }
        __syncthreads();

        // ---- scatter num += msg * attn via vector RED ----
        for (int i = tid; i < 1024; i += THREADS) {
            int el = i >> 4, q = i & 15;
            if (base + el < nE) {
                float a = attn_s[el];
                float4 m = *((const float4*)(xs + el * 68) + q);
                float* dst = num + (size_t)dest_s[el] * 64 + q * 4;
                asm volatile("red.global.add.v4.f32 [%0], {%1,%2,%3,%4};"
                             :: "l"(dst),
                                "f"(m.x * a), "f"(m.y * a), "f"(m.z * a), "f"(m.w * a)
                             : "memory");
            }
        }
    }
}

__global__ void cfconv_div(float* __restrict__ out, int total)
{
    int i = blockIdx.x * blockDim.x + threadIdx.x;
    if (i < total) {
        float den = g_den[i >> 6];
        float v = out[i];
        out[i] = (den > 0.f) ? v / den : v;
    }
}

extern "C" void kernel_launch(void* const* d_in, const int* in_sizes, int n_in,
                              void* d_out, int out_size)
{
    const float* atom_emb = (const float*)d_in[0];
    const float* edge_emb = (const float*)d_in[1];
    const float* W1       = (const float*)d_in[2];
    const float* b1       = (const float*)d_in[3];
    const float* W2       = (const float*)d_in[4];
    const float* b2       = (const float*)d_in[5];
    const float* coef     = (const float*)d_in[6];
    const void*  elist    = d_in[7];
    float* out = (float*)d_out;

    int nE     = in_sizes[1] / 64;   // edge count (dtype-independent)
    int nNodes = in_sizes[0] / 64;

    // zero num (d_out) and den scratch
    cudaMemsetAsync(d_out, 0, (size_t)out_size * sizeof(float), 0);
    void* denp = nullptr;
    cudaGetSymbolAddress(&denp, g_den);
    cudaMemsetAsync(denp, 0, (size_t)nNodes * sizeof(float), 0);

    cudaFuncSetAttribute(cfconv_main, cudaFuncAttributeMaxDynamicSharedMemorySize,
                         SMEM_BYTES);

    cfconv_main<<<444, THREADS, SMEM_BYTES, 0>>>(atom_emb, edge_emb, W1, b1, W2, b2,
                                                 coef, elist, out, nE);

    int total = nNodes * 64;
    cfconv_div<<<(total + 255) / 256, 256>>>(out, total);
}